// round 15
// baseline (speedup 1.0000x reference)
#include <cuda_runtime.h>
#include <cuda_fp16.h>
#include <cstdint>

// TreeLSTM B=64, L=10, H=E=256, V=64, TOTAL=2046.
//  - Gtab/Htab/Ctab tabulated per vocab id; level-9 U-GEMM tabulated (TL/TR)
//    with fp16 table copies for the L2-bound level-9 gather.
//  - levels 8..1: mma.sync fp16 single-pass, register-only gating epilogue.
//    Template CM chosen per level to minimize wave quantization
//    (lev8:64, lev7:32, lev6:128, lev5:64, lev4..1:32); 4-stage ring, 1 sync/chunk.

#define TOTAL_NODES 2046

// ---------------- scratch ----------------
__device__ __half g_h0[32768 * 256];
__device__ float  g_c0[32768 * 256];
__device__ __half g_h1[16384 * 256];
__device__ float  g_c1[16384 * 256];
__device__ float  g_hroot[128 * 256];    // fp32 h at level 1
__device__ float  g_Gtab[64 * 4 * 256];  // fp32 (mma epilogues)
__device__ __half g_Gh[64 * 4 * 256];    // fp16 copy (level 9)
__device__ float  g_Htab[64 * 256];
__device__ __half g_Ch[64 * 256];        // fp16 Ctab (level 9)
__device__ __half g_TLh[64 * 5 * 256];   // fp16 TL (level 9)
__device__ __half g_TRh[64 * 5 * 256];   // fp16 TR (level 9)
__device__ __half g_Bh[5 * 256 * 512];   // [g][n][k]  k = s*256+h, fp16 rounded

// ---------------- helpers ----------------
__device__ __forceinline__ float ftanh(float x) {
    float y; asm("tanh.approx.f32 %0, %1;" : "=f"(y) : "f"(x)); return y;
}
__device__ __forceinline__ float fsig(float x) { return 0.5f * ftanh(0.5f * x) + 0.5f; }

__device__ __forceinline__ uint32_t smem_u32(const void* p) {
    uint32_t a;
    asm("{ .reg .u64 t; cvta.to.shared.u64 t, %1; cvt.u32.u64 %0, t; }" : "=r"(a) : "l"(p));
    return a;
}

#define CP_ASYNC16(dst, src) \
    asm volatile("cp.async.cg.shared.global [%0], [%1], 16;" :: "r"(dst), "l"(src) : "memory")
#define CP_COMMIT() asm volatile("cp.async.commit_group;" ::: "memory")
#define CP_WAIT2()  asm volatile("cp.async.wait_group 2;" ::: "memory")

#define LDSM4(r, a) \
    asm volatile("ldmatrix.sync.aligned.m8n8.x4.shared.b16 {%0,%1,%2,%3}, [%4];" \
        : "=r"((r)[0]), "=r"((r)[1]), "=r"((r)[2]), "=r"((r)[3]) : "r"(a))

#define MMA16816(c, a, b0, b1) \
    asm volatile("mma.sync.aligned.m16n8k16.row.col.f32.f16.f16.f32 " \
        "{%0,%1,%2,%3}, {%4,%5,%6,%7}, {%8,%9}, {%0,%1,%2,%3};" \
        : "+f"((c)[0]), "+f"((c)[1]), "+f"((c)[2]), "+f"((c)[3]) \
        : "r"((a)[0]), "r"((a)[1]), "r"((a)[2]), "r"((a)[3]), "r"(b0), "r"(b1))

// ---------------- prep 1: Gtab (f32+f16), Htab, Ctab(f16) ------------------
__global__ void prep1_kernel(const float* __restrict__ emb,
                             const float* __restrict__ W,
                             const float* __restrict__ bW) {
    int v = blockIdx.x;
    int h = threadIdx.x;
    __shared__ float e[256];
    e[h] = emb[v * 256 + h];
    __syncthreads();
    float xg[4];
#pragma unroll
    for (int g = 0; g < 4; g++) {
        float s = bW[g * 256 + h];
        const float* Wg = W + g * 256 * 256 + h;
        for (int k = 0; k < 256; k++) s += e[k] * Wg[k * 256];
        xg[g] = s;
        g_Gtab[v * 1024 + g * 256 + h] = s;
        g_Gh[v * 1024 + g * 256 + h] = __float2half_rn(s);
    }
    float ig = fsig(xg[1]);
    float og = fsig(xg[2]);
    float ug = ftanh(xg[3]);
    float cc = ig * ug;
    g_Ch[v * 256 + h] = __float2half_rn(cc);
    g_Htab[v * 256 + h] = og * ftanh(cc);
}

// ---------------- prep 2: TL/TR (fp16)  (grid (64,10): v x (g,s)) ----------
__global__ void prep2_kernel(const float* __restrict__ U) {
    int v = blockIdx.x;
    int g = blockIdx.y >> 1;
    int s = blockIdx.y & 1;
    int k = threadIdx.x;
    __shared__ float hh[256];
    hh[k] = g_Htab[v * 256 + k];
    __syncthreads();
    __half* T = (s == 0) ? g_TLh : g_TRh;
    float acc = 0.0f;
    const float* Ug = U + ((g * 2 + s) * 256) * 256 + k;
    for (int h = 0; h < 256; h++) acc += hh[h] * Ug[h * 256];
    T[v * 1280 + g * 256 + k] = __float2half_rn(acc);
}

// ---------------- prep 3: B fp16 plane [g][n][k] ---------------------------
__global__ void prep3_kernel(const float* __restrict__ U) {
    int idx = blockIdx.x * blockDim.x + threadIdx.x;  // 5*256*512 = 655360
    if (idx >= 5 * 256 * 512) return;
    int k = idx & 511;
    int n = (idx >> 9) & 255;
    int g = idx >> 17;
    int s = k >> 8;
    int h = k & 255;
    g_Bh[idx] = __float2half_rn(U[((g * 2 + s) * 256 + h) * 256 + n]);
}

// ---------------- level 9: gather + gating (fp16 tables, 4 rows/block) -----
__global__ void level9_kernel(const int* __restrict__ node_ids,
                              __half* __restrict__ hout,
                              float* __restrict__ cout) {
    int t = threadIdx.x;
    int row = blockIdx.x * 4 + (t >> 6);
    int jq = (t & 63);                       // j = jq*4 .. jq*4+3
    int bb = row >> 9;
    int jn = row & 511;
    const int* nr = node_ids + bb * TOTAL_NODES;
    int id  = nr[510 + jn];
    int idL = nr[1022 + 2 * jn];
    int idR = nr[1023 + 2 * jn];
    const __half* tl = g_TLh + idL * 1280 + jq * 4;
    const __half* tr = g_TRh + idR * 1280 + jq * 4;
    const __half* gt = g_Gh + id * 1024 + jq * 4;
    // gate_map = [0,0,1,2,3]
    float p[5][4];
#pragma unroll
    for (int g = 0; g < 5; g++) {
        int gm = (g == 0 || g == 1) ? 0 : (g - 1);
        uint2 lu = *(const uint2*)(tl + g * 256);
        uint2 ru = *(const uint2*)(tr + g * 256);
        uint2 gu = *(const uint2*)(gt + gm * 256);
        float2 l0 = __half22float2(*(const __half2*)&lu.x);
        float2 l1 = __half22float2(*(const __half2*)&lu.y);
        float2 r0 = __half22float2(*(const __half2*)&ru.x);
        float2 r1 = __half22float2(*(const __half2*)&ru.y);
        float2 q0 = __half22float2(*(const __half2*)&gu.x);
        float2 q1 = __half22float2(*(const __half2*)&gu.y);
        p[g][0] = l0.x + r0.x + q0.x;
        p[g][1] = l0.y + r0.y + q0.y;
        p[g][2] = l1.x + r1.x + q1.x;
        p[g][3] = l1.y + r1.y + q1.y;
    }
    uint2 clu = *(const uint2*)(g_Ch + idL * 256 + jq * 4);
    uint2 cru = *(const uint2*)(g_Ch + idR * 256 + jq * 4);
    float2 cl0 = __half22float2(*(const __half2*)&clu.x);
    float2 cl1 = __half22float2(*(const __half2*)&clu.y);
    float2 cr0 = __half22float2(*(const __half2*)&cru.x);
    float2 cr1 = __half22float2(*(const __half2*)&cru.y);
    float clv[4] = {cl0.x, cl0.y, cl1.x, cl1.y};
    float crv[4] = {cr0.x, cr0.y, cr1.x, cr1.y};
    float cv[4], hv[4];
#pragma unroll
    for (int e = 0; e < 4; e++) {
        float cc = fsig(p[2][e]) * ftanh(p[4][e]) + fsig(p[0][e]) * clv[e]
                 + fsig(p[1][e]) * crv[e];
        cv[e] = cc;
        hv[e] = fsig(p[3][e]) * ftanh(cc);
    }
    size_t o = (size_t)row * 256 + jq * 4;
    *(float4*)(cout + o) = make_float4(cv[0], cv[1], cv[2], cv[3]);
    __half2 h01 = __floats2half2_rn(hv[0], hv[1]);
    __half2 h23 = __floats2half2_rn(hv[2], hv[3]);
    *(uint2*)(hout + o) = make_uint2(*(uint32_t*)&h01, *(uint32_t*)&h23);
}

// ---------------- mma.sync level kernel (levels 8..1) ----------------------
// CTA: CM rows x 64 j x 5 gates, K=512 in 8 chunks of 64. 256 threads.
// 8 warps: wr=wid>>2 m-half (CM/2 rows), wc=wid&3 j-slice (16 j). NI=CM/32.
// SMEM stage: A[CM][128B] B[320][128B], XOR seg-swizzle, 4-stage ring,
// ONE __syncthreads per chunk (lag<1 chunk; write stage (kc+2)&3 disjoint).
template <int CM>
__global__ void __launch_bounds__(256, 1)
mma_level_kernel(const __half* __restrict__ A_g,    // (rows,512) view
                 const float* __restrict__ c_prev,   // (rows,512) view
                 const int* __restrict__ node_ids,
                 __half* __restrict__ h_out,
                 float* __restrict__ c_out,
                 int lev) {
    constexpr int NI = CM / 32;             // m16-frags per warp
    constexpr int OFF_B = CM * 128;
    constexpr int STG = (CM + 320) * 128;
    constexpr int ACPT = CM / 32;           // A cp.async per thread

    extern __shared__ __align__(128) char dsm[];
    const uint32_t sbase = smem_u32(dsm);

    const int rbase = blockIdx.x * CM;
    const int jbase = blockIdx.y * 64;
    const int tid = threadIdx.x;
    const int wid = tid >> 5;
    const int wr = wid >> 2;       // m-half 0..1 (CM/2 rows each)
    const int wc = wid & 3;        // j-slice 0..3 (16 j each)
    const int lid = tid & 31;

    float acc[NI][5][2][4];
#pragma unroll
    for (int i = 0; i < NI; i++)
#pragma unroll
        for (int g = 0; g < 5; g++)
#pragma unroll
            for (int u = 0; u < 2; u++)
#pragma unroll
                for (int e = 0; e < 4; e++) acc[i][g][u][e] = 0.0f;

    const int rA = lid & 15;
    const int hA = lid >> 4;
    const int rB = (lid & 7) + ((lid >> 4) << 3);
    const int hB = (lid >> 3) & 1;
    const int rxA = rA & 7;
    const int rxB = rB & 7;

    auto load_chunk = [&](int kc, int st) {
        const uint32_t S = sbase + st * STG;
        const int k0 = kc * 64;
#pragma unroll
        for (int i = 0; i < ACPT; i++) {
            int c = i * 256 + tid;
            int r = c >> 3;
            int sg = c & 7;
            const __half* src = A_g + (size_t)(rbase + r) * 512 + k0 + sg * 8;
            CP_ASYNC16(S + r * 128 + ((sg ^ (r & 7)) << 4), src);
        }
#pragma unroll
        for (int i = 0; i < 10; i++) {
            int c = i * 256 + tid;
            int n = c >> 3;
            int sg = c & 7;
            int g = n >> 6;
            int jj = n & 63;
            const __half* src = g_Bh + (size_t)(g * 256 + jbase + jj) * 512 + k0 + sg * 8;
            CP_ASYNC16(S + OFF_B + n * 128 + ((sg ^ (n & 7)) << 4), src);
        }
    };

    load_chunk(0, 0); CP_COMMIT();
    load_chunk(1, 1); CP_COMMIT();

    for (int kc = 0; kc < 8; kc++) {
        if (kc + 2 < 8) load_chunk(kc + 2, (kc + 2) & 3);
        CP_COMMIT();
        CP_WAIT2();                            // chunk kc landed (this thread)
        __syncthreads();                       // publish all threads' chunk kc
        const uint32_t S = sbase + (kc & 3) * STG;

#pragma unroll
        for (int kk = 0; kk < 4; kk++) {
            uint32_t am[NI][4], bm[5][4];
            const int segA = ((kk << 1) + hA) ^ rxA;
            const int segB = ((kk << 1) + hB) ^ rxB;
#pragma unroll
            for (int i = 0; i < NI; i++)
                LDSM4(am[i], S + (wr * (CM / 2) + i * 16 + rA) * 128 + (segA << 4));
#pragma unroll
            for (int g = 0; g < 5; g++)
                LDSM4(bm[g], S + OFF_B + (g * 64 + wc * 16 + rB) * 128 + (segB << 4));
#pragma unroll
            for (int i = 0; i < NI; i++)
#pragma unroll
                for (int g = 0; g < 5; g++) {
                    MMA16816(acc[i][g][0], am[i], bm[g][0], bm[g][1]);
                    MMA16816(acc[i][g][1], am[i], bm[g][2], bm[g][3]);
                }
        }
    }

    // ---- register epilogue: gate + direct stores ----
    const int n = 1 << lev;
    const int off = n - 2;
#pragma unroll
    for (int i = 0; i < NI; i++) {
#pragma unroll
        for (int mh = 0; mh < 2; mh++) {
            int m = wr * (CM / 2) + i * 16 + (lid >> 2) + mh * 8;
            int row = rbase + m;
            int bb = row >> lev;
            int jn = row & (n - 1);
            int id = node_ids[bb * TOTAL_NODES + off + jn];
            const float* gt = g_Gtab + id * 1024;
#pragma unroll
            for (int u = 0; u < 2; u++) {
                int j = wc * 16 + u * 8 + (lid & 3) * 2;
                int jg = jbase + j;
                float2 g0 = *(const float2*)(gt + jg);
                float2 g1 = *(const float2*)(gt + 256 + jg);
                float2 g2 = *(const float2*)(gt + 512 + jg);
                float2 g3 = *(const float2*)(gt + 768 + jg);
                float2 cl = *(const float2*)(c_prev + (size_t)row * 512 + jg);
                float2 cr = *(const float2*)(c_prev + (size_t)row * 512 + 256 + jg);
                float p0x = acc[i][0][u][mh * 2 + 0] + g0.x;
                float p0y = acc[i][0][u][mh * 2 + 1] + g0.y;
                float p1x = acc[i][1][u][mh * 2 + 0] + g0.x;
                float p1y = acc[i][1][u][mh * 2 + 1] + g0.y;
                float p2x = acc[i][2][u][mh * 2 + 0] + g1.x;
                float p2y = acc[i][2][u][mh * 2 + 1] + g1.y;
                float p3x = acc[i][3][u][mh * 2 + 0] + g2.x;
                float p3y = acc[i][3][u][mh * 2 + 1] + g2.y;
                float p4x = acc[i][4][u][mh * 2 + 0] + g3.x;
                float p4y = acc[i][4][u][mh * 2 + 1] + g3.y;
                float2 cc;
                cc.x = fsig(p2x) * ftanh(p4x) + fsig(p0x) * cl.x + fsig(p1x) * cr.x;
                cc.y = fsig(p2y) * ftanh(p4y) + fsig(p0y) * cl.y + fsig(p1y) * cr.y;
                float hx = fsig(p3x) * ftanh(cc.x);
                float hy = fsig(p3y) * ftanh(cc.y);
                size_t o = (size_t)row * 256 + jg;
                *(float2*)(c_out + o) = cc;
                *(__half2*)(h_out + o) = __floats2half2_rn(hx, hy);
                if (lev == 1) *(float2*)(g_hroot + o) = make_float2(hx, hy);
            }
        }
    }
}

// ---------------- final: scores + root_hidden ------------------------------
__global__ void final_kernel(const float* __restrict__ Wsm,
                             const float* __restrict__ bs,
                             float* __restrict__ out, int out_size) {
    int b = blockIdx.x;
    int t = threadIdx.x;
    __shared__ float hs[512];
    for (int jj = t; jj < 512; jj += 256) {
        float v = g_hroot[b * 512 + jj];
        hs[jj] = v;
        if (out_size >= 192 + 64 * 512) out[192 + b * 512 + jj] = v;
    }
    __syncthreads();
    if (t < 3) {
        float s = bs[t];
        for (int jj = 0; jj < 512; jj++) s += hs[jj] * Wsm[jj * 3 + t];
        out[b * 3 + t] = s;
    }
}

extern "C" void kernel_launch(void* const* d_in, const int* in_sizes, int n_in,
                              void* d_out, int out_size) {
    const int* node_ids = (const int*)d_in[0];
    const float* emb = (const float*)d_in[1];
    const float* W = (const float*)d_in[2];
    const float* bW = (const float*)d_in[3];
    const float* U = (const float*)d_in[4];
    const float* Ws = (const float*)d_in[5];
    const float* bs = (const float*)d_in[6];
    float* out = (float*)d_out;

    __half *h0, *h1;
    float *c0, *c1;
    cudaGetSymbolAddress((void**)&h0, g_h0);
    cudaGetSymbolAddress((void**)&c0, g_c0);
    cudaGetSymbolAddress((void**)&h1, g_h1);
    cudaGetSymbolAddress((void**)&c1, g_c1);

    cudaFuncSetAttribute(mma_level_kernel<128>,
                         cudaFuncAttributeMaxDynamicSharedMemorySize, 4 * (128 + 320) * 128);
    cudaFuncSetAttribute(mma_level_kernel<64>,
                         cudaFuncAttributeMaxDynamicSharedMemorySize, 4 * (64 + 320) * 128);
    cudaFuncSetAttribute(mma_level_kernel<32>,
                         cudaFuncAttributeMaxDynamicSharedMemorySize, 4 * (32 + 320) * 128);

    prep1_kernel<<<64, 256>>>(emb, W, bW);
    prep2_kernel<<<dim3(64, 10), 256>>>(U);
    prep3_kernel<<<640, 1024>>>(U);

    level9_kernel<<<8192, 256>>>(node_ids, h0, c0);

    __half *hp = h0, *hc = h1;
    float *cp = c0, *cc = c1;
    for (int lev = 8; lev >= 1; lev--) {
        int rows = 64 << lev;
        if (lev == 6) {                       // 128 CTAs, 1 wave
            dim3 grid(rows / 128, 4);
            mma_level_kernel<128><<<grid, 256, 4 * (128 + 320) * 128>>>(
                hp, cp, node_ids, hc, cc, lev);
        } else if (lev == 8 || lev == 5) {    // quantization-optimal CM=64
            dim3 grid(rows / 64, 4);
            mma_level_kernel<64><<<grid, 256, 4 * (64 + 320) * 128>>>(
                hp, cp, node_ids, hc, cc, lev);
        } else {                               // lev 7, 4..1: CM=32
            dim3 grid(rows / 32, 4);
            mma_level_kernel<32><<<grid, 256, 4 * (32 + 320) * 128>>>(
                hp, cp, node_ids, hc, cc, lev);
        }
        __half* t1 = hp; hp = hc; hc = t1;
        float* t2 = cp; cp = cc; cc = t2;
    }
    final_kernel<<<64, 256>>>(Ws, bs, out, out_size);
}